// round 16
// baseline (speedup 1.0000x reference)
#include <cuda_runtime.h>
#include <cstdint>

#define NHEADS   16
#define M_TBL    524288
#define D_IN     32
#define HID      64
#define NOUT     3
#define TILE     128             // per group
#define THREADS  512             // 2 groups x 256 threads
#define NT       16384           // 128-pt tiles total
#define GRID     148             // 1 CTA per SM
#define GSTEP    (GRID * 2)      // 296 group-slots
#define ITERS    56              // ceil(16384 / 296)
#define STR      128

__constant__ __align__(16) float cW1[D_IN * HID];
__constant__ __align__(16) float cW2[HID * HID];
__constant__ __align__(16) float cW3[HID * HID];
__constant__ __align__(16) float cW4[HID * NOUT];
__constant__ __align__(16) float cb1[HID];
__constant__ __align__(16) float cb2[HID];
__constant__ __align__(16) float cb3[HID];
__constant__ __align__(16) float cb4[NOUT];

#define BUF_FLOATS (HID * STR)               // 8192 floats = 32 KB
#define SMEM_BYTES (4 * BUF_FLOATS * 4)      // 131072 -> 1 CTA/SM

#define FMA2(acc, a, b) \
    asm("fma.rn.f32x2 %0, %1, %2, %0;" : "+l"(acc) : "l"(a), "l"(b))
#define PACK2(d, s) \
    asm("mov.b64 %0, {%1, %1};" : "=l"(d) : "f"(s))
#define UNPACK2(lo, hi, s) \
    asm("mov.b64 {%0, %1}, %2;" : "=f"(lo), "=f"(hi) : "l"(s))
#define GBAR(id) \
    asm volatile("bar.sync %0, 256;" :: "r"(id) : "memory")

typedef unsigned long long ull;

// One layer over a 128-pt tile, ping-pong (read A, write B).
// Group-warp owns j-block [jw, jw+8); lane owns 4 points lane4..+3.
// acc[p*4+jp] = j-pair (jw+2jp, jw+2jp+1) for point lane4+p.
// Per k-step: 1 LDS.128 + 2 LDC.128 + 4 PACK2 + 16 FFMA2.
template<int L, int K>
__device__ __forceinline__ void layer(const float* __restrict__ A,
                                      float* __restrict__ B,
                                      int jw, int lane4)
{
    ull acc[16];
    {
        ulonglong2 b01, b23;
        if constexpr (L == 1) {
            b01 = *reinterpret_cast<const ulonglong2*>(&cb1[jw]);
            b23 = *reinterpret_cast<const ulonglong2*>(&cb1[jw + 4]);
        } else if constexpr (L == 2) {
            b01 = *reinterpret_cast<const ulonglong2*>(&cb2[jw]);
            b23 = *reinterpret_cast<const ulonglong2*>(&cb2[jw + 4]);
        } else {
            b01 = *reinterpret_cast<const ulonglong2*>(&cb3[jw]);
            b23 = *reinterpret_cast<const ulonglong2*>(&cb3[jw + 4]);
        }
        #pragma unroll
        for (int p = 0; p < 4; p++) {
            acc[p*4 + 0] = b01.x; acc[p*4 + 1] = b01.y;
            acc[p*4 + 2] = b23.x; acc[p*4 + 3] = b23.y;
        }
    }

    #pragma unroll 8
    for (int k = 0; k < K; k++) {
        const float4 a = *reinterpret_cast<const float4*>(&A[k * STR + lane4]);
        ull d0, d1, d2, d3;
        PACK2(d0, a.x); PACK2(d1, a.y); PACK2(d2, a.z); PACK2(d3, a.w);

        ulonglong2 w01, w23;
        if constexpr (L == 1) {
            w01 = *reinterpret_cast<const ulonglong2*>(&cW1[k * HID + jw]);
            w23 = *reinterpret_cast<const ulonglong2*>(&cW1[k * HID + jw + 4]);
        } else if constexpr (L == 2) {
            w01 = *reinterpret_cast<const ulonglong2*>(&cW2[k * HID + jw]);
            w23 = *reinterpret_cast<const ulonglong2*>(&cW2[k * HID + jw + 4]);
        } else {
            w01 = *reinterpret_cast<const ulonglong2*>(&cW3[k * HID + jw]);
            w23 = *reinterpret_cast<const ulonglong2*>(&cW3[k * HID + jw + 4]);
        }

        FMA2(acc[ 0], d0, w01.x); FMA2(acc[ 1], d0, w01.y);
        FMA2(acc[ 2], d0, w23.x); FMA2(acc[ 3], d0, w23.y);
        FMA2(acc[ 4], d1, w01.x); FMA2(acc[ 5], d1, w01.y);
        FMA2(acc[ 6], d1, w23.x); FMA2(acc[ 7], d1, w23.y);
        FMA2(acc[ 8], d2, w01.x); FMA2(acc[ 9], d2, w01.y);
        FMA2(acc[10], d2, w23.x); FMA2(acc[11], d2, w23.y);
        FMA2(acc[12], d3, w01.x); FMA2(acc[13], d3, w01.y);
        FMA2(acc[14], d3, w23.x); FMA2(acc[15], d3, w23.y);
    }

    // relu + store this warp's 8 rows
    #pragma unroll
    for (int jp = 0; jp < 4; jp++) {
        float lo[4], hi[4];
        #pragma unroll
        for (int p = 0; p < 4; p++) {
            UNPACK2(lo[p], hi[p], acc[p*4 + jp]);
            lo[p] = fmaxf(lo[p], 0.0f);
            hi[p] = fmaxf(hi[p], 0.0f);
        }
        const int j0 = jw + 2 * jp;
        *reinterpret_cast<float4*>(&B[j0 * STR + lane4]) =
            make_float4(lo[0], lo[1], lo[2], lo[3]);
        *reinterpret_cast<float4*>(&B[(j0 + 1) * STR + lane4]) =
            make_float4(hi[0], hi[1], hi[2], hi[3]);
    }
}

__global__ __launch_bounds__(THREADS, 1)
void ngp_2grp_kernel(const int* __restrict__ idx,
                     const float* __restrict__ tables,
                     float* __restrict__ out)
{
    extern __shared__ float sm[];

    const int tid   = threadIdx.x;
    const int g     = tid >> 8;            // group 0 / 1
    const int tg    = tid & 255;           // tid within group
    const int lane  = tid & 31;
    const int jw    = ((tid >> 5) & 7) * 8;  // group-warp's 8 j-cols
    const int lane4 = lane * 4;
    const int gp = tg >> 1;                // gather: point (2 thr/pt)
    const int gh = (tg & 1) * 8;           // gather: head start

    float* buf0 = sm + g * 2 * BUF_FLOATS;
    float* buf1 = buf0 + BUF_FLOATS;
    const int barid = 1 + g;               // named barrier per group

    // ---- prologue: gather first tile into buf0 rows 0..31 ----
    {
        const long t0 = (long)blockIdx.x * 2 + g;
        const int* ip = idx + (t0 * TILE + gp) * NHEADS + gh;
        const int4 i0 = *reinterpret_cast<const int4*>(ip);
        const int4 i1 = *reinterpret_cast<const int4*>(ip + 4);
        const int ii[8] = { i0.x, i0.y, i0.z, i0.w, i1.x, i1.y, i1.z, i1.w };
        #pragma unroll
        for (int i = 0; i < 8; i++) {
            const float2 v = *reinterpret_cast<const float2*>(
                tables + ((long)(gh + i) * M_TBL + ii[i]) * 2);
            buf0[(2 * (gh + i)    ) * STR + gp] = v.x;
            buf0[(2 * (gh + i) + 1) * STR + gp] = v.y;
        }
    }
    __syncthreads();

    for (int it = 0; it < ITERS; it++) {
        const long t = (long)blockIdx.x * 2 + g + (long)it * GSTEP;
        const bool valid = (t < NT);
        const bool nextValid = (t + GSTEP < NT);
        const long pbase = t * TILE;

        // idx LDG for NEXT tile (hidden under layer 1)
        int4 ni0 = make_int4(0,0,0,0), ni1 = make_int4(0,0,0,0);
        if (nextValid) {
            const int* ip = idx + ((t + GSTEP) * TILE + gp) * NHEADS + gh;
            ni0 = *reinterpret_cast<const int4*>(ip);
            ni1 = *reinterpret_cast<const int4*>(ip + 4);
        }

        // layer 1: buf0 -> buf1
        if (valid) layer<1, D_IN>(buf0, buf1, jw, lane4);
        GBAR(barid);                                   // [1]

        // table LDGs for next tile (hidden under L2/L3)
        float2 nv[8];
        if (nextValid) {
            const int nii[8] = { ni0.x, ni0.y, ni0.z, ni0.w,
                                 ni1.x, ni1.y, ni1.z, ni1.w };
            #pragma unroll
            for (int i = 0; i < 8; i++)
                nv[i] = *reinterpret_cast<const float2*>(
                    tables + ((long)(gh + i) * M_TBL + nii[i]) * 2);
        }

        // layer 2: buf1 -> buf0
        if (valid) layer<2, HID>(buf1, buf0, jw, lane4);
        GBAR(barid);                                   // [2]

        // layer 3: buf0 -> buf1
        if (valid) layer<3, HID>(buf0, buf1, jw, lane4);
        GBAR(barid);                                   // [3]

        // buf0 is dead: park NEXT tile's gather (concurrent with L4)
        if (nextValid) {
            #pragma unroll
            for (int i = 0; i < 8; i++) {
                buf0[(2 * (gh + i)    ) * STR + gp] = nv[i].x;
                buf0[(2 * (gh + i) + 1) * STR + gp] = nv[i].y;
            }
        }

        // layer 4: buf1 -> out, 2 threads/point (k halves) + shfl combine
        if (valid) {
            const int p  = tg >> 1;
            const int kb = (tg & 1) * 32;
            float o0 = 0.f, o1 = 0.f, o2 = 0.f;
            #pragma unroll 8
            for (int k = kb; k < kb + 32; k++) {
                const float a = buf1[k * STR + p];
                o0 = fmaf(a, cW4[k * NOUT + 0], o0);
                o1 = fmaf(a, cW4[k * NOUT + 1], o1);
                o2 = fmaf(a, cW4[k * NOUT + 2], o2);
            }
            o0 += __shfl_down_sync(0xFFFFFFFFu, o0, 1);
            o1 += __shfl_down_sync(0xFFFFFFFFu, o1, 1);
            o2 += __shfl_down_sync(0xFFFFFFFFu, o2, 1);
            if ((tg & 1) == 0) {
                float* op = out + (pbase + p) * NOUT;
                op[0] = o0 + cb4[0];
                op[1] = o1 + cb4[1];
                op[2] = o2 + cb4[2];
            }
        }

        // joint resync: bounds layer drift between groups (const locality)
        __syncthreads();                               // [4]
    }
}

extern "C" void kernel_launch(void* const* d_in, const int* in_sizes, int n_in,
                              void* d_out, int out_size)
{
    static int init = 0;
    if (!init) {
        cudaFuncSetAttribute(ngp_2grp_kernel,
                             cudaFuncAttributeMaxDynamicSharedMemorySize,
                             SMEM_BYTES);
        init = 1;
    }

    cudaMemcpyToSymbolAsync(cW1, d_in[2], D_IN*HID*sizeof(float), 0,
                            cudaMemcpyDeviceToDevice, 0);
    cudaMemcpyToSymbolAsync(cb1, d_in[3], HID*sizeof(float), 0,
                            cudaMemcpyDeviceToDevice, 0);
    cudaMemcpyToSymbolAsync(cW2, d_in[4], HID*HID*sizeof(float), 0,
                            cudaMemcpyDeviceToDevice, 0);
    cudaMemcpyToSymbolAsync(cb2, d_in[5], HID*sizeof(float), 0,
                            cudaMemcpyDeviceToDevice, 0);
    cudaMemcpyToSymbolAsync(cW3, d_in[6], HID*HID*sizeof(float), 0,
                            cudaMemcpyDeviceToDevice, 0);
    cudaMemcpyToSymbolAsync(cb3, d_in[7], HID*sizeof(float), 0,
                            cudaMemcpyDeviceToDevice, 0);
    cudaMemcpyToSymbolAsync(cW4, d_in[8], HID*NOUT*sizeof(float), 0,
                            cudaMemcpyDeviceToDevice, 0);
    cudaMemcpyToSymbolAsync(cb4, d_in[9], NOUT*sizeof(float), 0,
                            cudaMemcpyDeviceToDevice, 0);

    ngp_2grp_kernel<<<GRID, THREADS, SMEM_BYTES>>>(
        (const int*)d_in[0], (const float*)d_in[1], (float*)d_out);
}